// round 17
// baseline (speedup 1.0000x reference)
#include <cuda_runtime.h>
#include <cuda_fp16.h>
#include <math.h>

#define N_  50000
#define T_  25
#define A_  16
#define H_  128
#define I_  64
#define E_  800000
#define NTILES 1563   // ceil(N/32)
#define GRID_GRU 296  // 2 CTAs/SM * 148 SMs

// Scratch (no allocations allowed): device globals.
__device__ float g_xln[N_ * H_];
__device__ float g_agg[N_ * H_];
__device__ float g_deg_out[N_];
__device__ float g_deg_in[N_];

__device__ __forceinline__ float softplusf(float x) {
    return x > 0.f ? x + log1pf(expf(-x)) : log1pf(expf(x));
}

// ===========================================================================
// GRU via mma.sync fp16 (HMMA), single-pass, 2 CTAs/SM, persistent, fused LN.
// R17 change: ldmB via ldmatrix.x4 — r+z fragments of one kstep in one
// instruction (lane groups 0-1 -> r tile, 2-3 -> z tile), n fragments of two
// adjacent ksteps in one instruction. LDSM/warp/step: 43 -> 30 (L1-bound fix).
// smem layout unchanged:
//   WHH 0..98304, BX 98304..110592 (aliased by AH/AX/LNbuf after hoist)
// ===========================================================================
#define OFF_WHH   0
#define OFF_BX    98304
#define OFF_AH    98304
#define OFF_AX    106496
#define GRU_SMEM  110592

__device__ __forceinline__ unsigned s2u(const void* p) {
    unsigned a;
    asm("{ .reg .u64 t; cvta.to.shared.u64 t, %1; cvt.u32.u64 %0, t; }"
        : "=r"(a) : "l"(p));
    return a;
}
__device__ __forceinline__ int offW(int k, int c) {   // row stride 768B
    return k * 768 + ((((c >> 3) ^ (k & 7)) << 4) + ((c & 7) << 1));
}
__device__ __forceinline__ int offA(int r, int k) {   // row stride 256B
    return r * 256 + ((((k >> 3) ^ (r & 7)) << 4) + ((k & 7) << 1));
}
__device__ __forceinline__ int offX(int r, int k) {   // row stride 64B
    return r * 64 + ((((k >> 3) ^ (r & 3)) << 4) + ((k & 7) << 1));
}

__device__ __forceinline__ void ldmA(unsigned addr, unsigned& a0, unsigned& a1,
                                     unsigned& a2, unsigned& a3) {
    asm volatile("ldmatrix.sync.aligned.m8n8.x4.shared.b16 {%0,%1,%2,%3}, [%4];"
                 : "=r"(a0), "=r"(a1), "=r"(a2), "=r"(a3) : "r"(addr));
}
__device__ __forceinline__ void ldmB(unsigned addr, unsigned& b0, unsigned& b1) {
    asm volatile("ldmatrix.sync.aligned.m8n8.x2.trans.shared.b16 {%0,%1}, [%2];"
                 : "=r"(b0), "=r"(b1) : "r"(addr));
}
__device__ __forceinline__ void ldmB4(unsigned addr, unsigned& b0, unsigned& b1,
                                      unsigned& b2, unsigned& b3) {
    asm volatile("ldmatrix.sync.aligned.m8n8.x4.trans.shared.b16 {%0,%1,%2,%3}, [%4];"
                 : "=r"(b0), "=r"(b1), "=r"(b2), "=r"(b3) : "r"(addr));
}
__device__ __forceinline__ void mma16816(float d[4], unsigned a0, unsigned a1,
                                         unsigned a2, unsigned a3,
                                         unsigned b0, unsigned b1) {
    asm volatile(
        "mma.sync.aligned.m16n8k16.row.col.f32.f16.f16.f32 "
        "{%0,%1,%2,%3},{%4,%5,%6,%7},{%8,%9},{%0,%1,%2,%3};"
        : "+f"(d[0]), "+f"(d[1]), "+f"(d[2]), "+f"(d[3])
        : "r"(a0), "r"(a1), "r"(a2), "r"(a3), "r"(b0), "r"(b1));
}

__device__ __forceinline__ unsigned short fh(float x) {
    return __half_as_ushort(__float2half(x));
}
__device__ __forceinline__ float tanha(float x) {
    float y;
    asm("tanh.approx.f32 %0, %1;" : "=f"(y) : "f"(x));
    return y;
}

__global__ void __launch_bounds__(512, 2) gru_mma_kernel(
    const float* __restrict__ actions,  // (N, T, A)
    const float* __restrict__ hidden,   // (1, N, H)
    const float* __restrict__ W_ih,     // (3H, A)
    const float* __restrict__ W_hh,     // (3H, H)
    const float* __restrict__ b_ih,     // (3H)
    const float* __restrict__ b_hh,     // (3H)
    const float* __restrict__ ln_g,     // (H)
    const float* __restrict__ ln_b,     // (H)
    float* __restrict__ h_out)          // (N, H)
{
    extern __shared__ char sm[];
    const unsigned sb = s2u(sm);
    const int tid  = threadIdx.x;
    const int w    = tid >> 5;        // warp 0..15
    const int lane = tid & 31;

    // ================= stage W once per block ==============
    for (int idx = tid; idx < 384 * 128; idx += 512) {
        int c = idx >> 7, k = idx & 127;
        *(unsigned short*)(sm + OFF_WHH + offW(k, c)) = fh(__ldg(W_hh + idx));
    }
    for (int idx = tid; idx < 384 * 16; idx += 512) {
        int c = idx >> 4, a = idx & 15;
        *(unsigned short*)(sm + OFF_BX + offW(a, c)) = fh(__ldg(W_ih + idx));
    }
    __syncthreads();

    // ================= hoist W_ih fragments (6 regs) =========
    const int l15 = lane & 15, l7 = lane & 7, hb = lane >> 4;
    const unsigned bRow = (unsigned)(l15 * 768);
    int ctile[3];
    #pragma unroll
    for (int g = 0; g < 3; ++g) ctile[g] = (((g << 4) + w) ^ l7) << 4;

    unsigned bx[3][2];
    {
        unsigned kb = sb + OFF_BX + bRow;
        #pragma unroll
        for (int g = 0; g < 3; ++g)
            ldmB(kb + ctile[g], bx[g][0], bx[g][1]);
    }

    // ---- x4 ldmB address bases (per-lane) ----
    // rz: lane groups 0-1 -> gate r (tile w), 2-3 -> gate z (tile 16+w)
    // n:  lane groups 0-1 -> kstep ks, 2-3 -> kstep ks+1 (tile 32+w)
    const int grpk = (lane >> 3) & 1;   // k-lo/k-hi 8 rows
    const int gsel = lane >> 4;         // fragment select
    const unsigned rzBase = (unsigned)((grpk * 8 + l7) * 768 +
                            ((((gsel ? 16 : 0) + w) ^ l7) << 4));
    const unsigned nBase  = (unsigned)((grpk * 8 + l7) * 768 + gsel * 12288 +
                            (((32 + w) ^ l7) << 4));

    // ---- per-thread unit/bias setup (tile-invariant) ----
    const int tr = lane >> 2;
    const int j0 = (w << 3) + ((lane & 3) << 1);
    float br[2], bz[2], bin[2], bhn[2];
    #pragma unroll
    for (int q = 0; q < 2; ++q) {
        int j = j0 + q;
        br[q]  = __ldg(b_ih + j)       + __ldg(b_hh + j);
        bz[q]  = __ldg(b_ih + 128 + j) + __ldg(b_hh + 128 + j);
        bin[q] = __ldg(b_ih + 256 + j);
        bhn[q] = __ldg(b_hh + 256 + j);
    }
    float* bufA = (float*)(sm + OFF_AH);   // 16r x 128 f32 LN buffer (aliases AH)

    __syncthreads();   // bx hoist reads done

    // ===================== persistent tile loop ============================
    for (int tile = blockIdx.x; tile < NTILES; tile += GRID_GRU) {
        const int grow0 = tile << 5;

        // ---- stage A tiles ----
        for (int idx = tid; idx < 32 * 128; idx += 512) {
            int r = idx >> 7, k = idx & 127;
            int gr = grow0 + r; if (gr >= N_) gr = N_ - 1;
            float v = __ldg(hidden + (size_t)gr * H_ + k);
            *(unsigned short*)(sm + OFF_AH + offA(r, k)) = fh(v);
        }
        {   // x_0
            int r = tid >> 4, a = tid & 15;
            int gr = grow0 + r; if (gr >= N_) gr = N_ - 1;
            float v = __ldg(actions + (size_t)gr * (T_ * A_) + a);
            *(unsigned short*)(sm + OFF_AX + offX(r, a)) = fh(v);
        }

        // ---- h state in fp32 registers ----
        float hold[8];
        #pragma unroll
        for (int rt = 0; rt < 2; ++rt)
            #pragma unroll
            for (int s = 0; s < 2; ++s) {
                int gr = grow0 + 16 * rt + tr + 8 * s;
                if (gr >= N_) gr = N_ - 1;
                float2 hv = *reinterpret_cast<const float2*>(hidden + (size_t)gr * H_ + j0);
                hold[rt * 4 + s * 2]     = hv.x;
                hold[rt * 4 + s * 2 + 1] = hv.y;
            }

        const int xr = tid >> 4, xa = tid & 15;
        int xgr = grow0 + xr; if (xgr >= N_) xgr = N_ - 1;
        const float* xsrc = actions + (size_t)xgr * (T_ * A_) + xa;

        __syncthreads();

        for (int t = 0; t < T_; ++t) {
            float xpre = 0.f;
            if (t + 1 < T_) xpre = __ldg(xsrc + (t + 1) * A_);

            float accR[2][4] = {}, accZ[2][4] = {}, accN[2][4] = {}, accNI[2][4] = {};

            // ---- h pass: 8 ksteps; ldmB.x4 (r+z per ks; n per ks-pair) ----
            unsigned nn[4];
            #pragma unroll
            for (int ks = 0; ks < 8; ++ks) {
                unsigned rz[4];
                ldmB4(sb + OFF_WHH + rzBase + (unsigned)(ks * 12288),
                      rz[0], rz[1], rz[2], rz[3]);
                if ((ks & 1) == 0)
                    ldmB4(sb + OFF_WHH + nBase + (unsigned)((ks >> 1) * 24576),
                          nn[0], nn[1], nn[2], nn[3]);
                const unsigned n0 = (ks & 1) ? nn[2] : nn[0];
                const unsigned n1 = (ks & 1) ? nn[3] : nn[1];
                unsigned koff = (unsigned)((((ks << 1) + hb) ^ l7) << 4);
                #pragma unroll
                for (int rt = 0; rt < 2; ++rt) {
                    unsigned abase = sb + OFF_AH + (unsigned)((16 * rt + l15) * 256) + koff;
                    unsigned ah0, ah1, ah2, ah3;
                    ldmA(abase, ah0, ah1, ah2, ah3);
                    mma16816(accR[rt], ah0, ah1, ah2, ah3, rz[0], rz[1]);
                    mma16816(accZ[rt], ah0, ah1, ah2, ah3, rz[2], rz[3]);
                    mma16816(accN[rt], ah0, ah1, ah2, ah3, n0, n1);
                }
            }
            // ---- x pass: weights in regs ----
            #pragma unroll
            for (int rt = 0; rt < 2; ++rt) {
                unsigned xbase = sb + OFF_AX + (unsigned)((16 * rt + l15) * 64);
                unsigned xh0, xh1, xh2, xh3;
                ldmA(xbase + (unsigned)((hb ^ (l15 & 3)) << 4), xh0, xh1, xh2, xh3);
                #pragma unroll
                for (int g = 0; g < 3; ++g) {
                    float* dst = (g == 0) ? accR[rt] : (g == 1) ? accZ[rt] : accNI[rt];
                    mma16816(dst, xh0, xh1, xh2, xh3, bx[g][0], bx[g][1]);
                }
            }

            __syncthreads();   // all smem reads of AH/AX complete

            // ---- gate math ----
            #pragma unroll
            for (int rt = 0; rt < 2; ++rt)
                #pragma unroll
                for (int s = 0; s < 2; ++s) {
                    float hn2[2];
                    #pragma unroll
                    for (int q = 0; q < 2; ++q) {
                        int i = s * 2 + q;
                        float pr = accR[rt][i] + br[q];
                        float pz = accZ[rt][i] + bz[q];
                        float gn = accN[rt][i] + bhn[q];
                        float gi = accNI[rt][i] + bin[q];
                        float rg = fmaf(0.5f, tanha(0.5f * pr), 0.5f);
                        float zg = fmaf(0.5f, tanha(0.5f * pz), 0.5f);
                        float pre = fmaf(rg, gn, gi);
                        float ng = tanha(pre);
                        float hn = fmaf(zg, hold[rt * 4 + i] - ng, ng);
                        hold[rt * 4 + i] = hn;
                        hn2[q] = hn;
                    }
                    int row = 16 * rt + tr + (s << 3);
                    if (t == T_ - 1) {
                        if (rt == 0)
                            *reinterpret_cast<float2*>(bufA + (row << 7) + j0) =
                                make_float2(hn2[0], hn2[1]);
                    } else {
                        int o = offA(row, j0);
                        unsigned uh = (unsigned)fh(hn2[0]) | ((unsigned)fh(hn2[1]) << 16);
                        *(unsigned*)(sm + OFF_AH + o) = uh;
                    }
                }

            if (t + 1 < T_) {
                *(unsigned short*)(sm + OFF_AX + offX(xr, xa)) = fh(xpre);
                __syncthreads();
            }
        }

        // ================= fused LayerNorm + src-scale ======================
        #pragma unroll
        for (int pass = 0; pass < 2; ++pass) {
            __syncthreads();   // buffer writes visible
            float4 v = reinterpret_cast<float4*>(bufA)[(w << 5) + lane];
            float s  = v.x + v.y + v.z + v.w;
            float ss = v.x * v.x + v.y * v.y + v.z * v.z + v.w * v.w;
            #pragma unroll
            for (int o = 16; o > 0; o >>= 1) {
                s  += __shfl_xor_sync(0xffffffffu, s, o);
                ss += __shfl_xor_sync(0xffffffffu, ss, o);
            }
            float mu  = s * (1.f / 128.f);
            float var = ss * (1.f / 128.f) - mu * mu;
            float inv = rsqrtf(var + 1e-5f);
            int grow = grow0 + pass * 16 + w;
            if (grow < N_) {
                float dg = g_deg_out[grow];
                float ns = dg > 0.f ? rsqrtf(dg) : 1.f;
                float4 g4 = __ldg(reinterpret_cast<const float4*>(ln_g) + lane);
                float4 b4 = __ldg(reinterpret_cast<const float4*>(ln_b) + lane);
                float4 o4;
                o4.x = ((v.x - mu) * inv * g4.x + b4.x) * ns;
                o4.y = ((v.y - mu) * inv * g4.y + b4.y) * ns;
                o4.z = ((v.z - mu) * inv * g4.z + b4.z) * ns;
                o4.w = ((v.w - mu) * inv * g4.w + b4.w) * ns;
                *reinterpret_cast<float4*>(g_xln + (size_t)grow * H_ + (lane << 2)) = o4;
                *reinterpret_cast<float4*>(h_out + (size_t)grow * H_ + (lane << 2)) = v;
            }
            __syncthreads();   // pass reads done
            if (pass == 0) {
                #pragma unroll
                for (int s2 = 0; s2 < 2; ++s2) {
                    int browi = tr + (s2 << 3);
                    *reinterpret_cast<float2*>(bufA + (browi << 7) + j0) =
                        make_float2(hold[4 + s2 * 2], hold[4 + s2 * 2 + 1]);
                }
            }
        }
        __syncthreads();   // LN done before next tile restages AH
    }
}

// ===========================================================================
// Small graph kernels
// ===========================================================================
__global__ void zero_deg_kernel() {
    int i = blockIdx.x * 256 + threadIdx.x;
    if (i < N_) { g_deg_in[i] = 0.f; g_deg_out[i] = 0.f; }
}
__global__ void zero_agg_kernel() {
    int i = blockIdx.x * 256 + threadIdx.x;
    reinterpret_cast<float4*>(g_agg)[i] = make_float4(0.f, 0.f, 0.f, 0.f);
}
__global__ void degree_kernel(const int* __restrict__ src, const int* __restrict__ dst) {
    int e = blockIdx.x * 256 + threadIdx.x;
    atomicAdd(&g_deg_out[__ldg(src + e)], 1.f);
    atomicAdd(&g_deg_in[__ldg(dst + e)], 1.f);
}
__global__ void scatter_kernel(const int* __restrict__ src, const int* __restrict__ dst) {
    int gid = blockIdx.x * 256 + threadIdx.x;
    int e = gid >> 5, c = gid & 31;
    int s = __ldg(src + e), d = __ldg(dst + e);
    float4 v = *reinterpret_cast<const float4*>(g_xln + (size_t)s * H_ + (c << 2));
    atomicAdd(reinterpret_cast<float4*>(g_agg + (size_t)d * H_ + (c << 2)), v);
}

// ===========================================================================
// Persistent fused GraphConv + heads (unchanged).
// ===========================================================================
#define FIN_SMEM ((128 * 32 + 128 * 64) * 16 + 2 * 16 * 128 * 4)   // 212992

__global__ void __launch_bounds__(512, 1) final_kernel(
    const float* __restrict__ Wg,    const float* __restrict__ bg,
    const float* __restrict__ Wa_mu, const float* __restrict__ ba_mu,
    const float* __restrict__ Wa_sd, const float* __restrict__ ba_sd,
    const float* __restrict__ Wz_mu, const float* __restrict__ bz_mu,
    const float* __restrict__ Wz_sd, const float* __restrict__ bz_sd,
    float* __restrict__ out)
{
    extern __shared__ float fsm[];
    float4* Wg4 = reinterpret_cast<float4*>(fsm);            // [128][32]
    float4* Wt4 = Wg4 + 128 * 32;                            // [128][64]
    float*  tb  = reinterpret_cast<float*>(Wt4 + 128 * 64);  // [16][128]
    float*  yb  = tb + 16 * 128;                             // [16][128]

    const int tid  = threadIdx.x;
    const int rw   = tid >> 5;
    const int lane = tid & 31;

    for (int idx = tid; idx < 128 * 32; idx += 512) {
        int k = idx >> 5, j = idx & 31;
        Wg4[(k << 5) + j] = make_float4(
            __ldg(Wg + (k << 7) + j),      __ldg(Wg + (k << 7) + j + 32),
            __ldg(Wg + (k << 7) + j + 64), __ldg(Wg + (k << 7) + j + 96));
    }
    for (int idx = tid; idx < 128 * 64; idx += 512) {
        int k = idx >> 6, i = idx & 63;
        int o = (i << 7) + k;
        Wt4[(k << 6) + i] = make_float4(__ldg(Wa_mu + o), __ldg(Wa_sd + o),
                                        __ldg(Wz_mu + o), __ldg(Wz_sd + o));
    }
    __syncthreads();

    float bgq[4];
    #pragma unroll
    for (int q = 0; q < 4; ++q) bgq[q] = __ldg(bg + lane + (q << 5));
    float bam[2], bas[2], bzm[2], bzs[2];
    #pragma unroll
    for (int q = 0; q < 2; ++q) {
        int i = lane + (q << 5);
        bam[q] = __ldg(ba_mu + i);  bas[q] = __ldg(ba_sd + i);
        bzm[q] = __ldg(bz_mu + i);  bzs[q] = __ldg(bz_sd + i);
    }

    const int NI = N_ * I_;
    float* tbr = tb + (rw << 7);
    float* ybr = yb + (rw << 7);

    for (int tile = blockIdx.x; tile < N_ / 16; tile += 148) {
        int row = (tile << 4) + rw;

        {
            float dg = g_deg_in[row];
            float nd = dg > 0.f ? rsqrtf(dg) : 1.f;
            float4 v = *reinterpret_cast<const float4*>(g_agg + (size_t)row * H_ + (lane << 2));
            v.x *= nd; v.y *= nd; v.z *= nd; v.w *= nd;
            *reinterpret_cast<float4*>(tbr + (lane << 2)) = v;
        }
        __syncwarp();

        float acc[4] = {0.f, 0.f, 0.f, 0.f};
        #pragma unroll 4
        for (int k = 0; k < 128; ++k) {
            float tv = tbr[k];
            float4 wg = Wg4[(k << 5) + lane];
            acc[0] = fmaf(tv, wg.x, acc[0]);
            acc[1] = fmaf(tv, wg.y, acc[1]);
            acc[2] = fmaf(tv, wg.z, acc[2]);
            acc[3] = fmaf(tv, wg.w, acc[3]);
        }
        #pragma unroll
        for (int q = 0; q < 4; ++q)
            ybr[lane + (q << 5)] = acc[q] + bgq[q];
        __syncwarp();

        float am[2] = {0.f, 0.f}, as[2] = {0.f, 0.f};
        float zm[2] = {0.f, 0.f}, zs[2] = {0.f, 0.f};
        #pragma unroll 4
        for (int k = 0; k < 128; ++k) {
            float yv = ybr[k];
            float4 w0 = Wt4[(k << 6) + lane];
            float4 w1 = Wt4[(k << 6) + lane + 32];
            am[0] = fmaf(yv, w0.x, am[0]);  am[1] = fmaf(yv, w1.x, am[1]);
            as[0] = fmaf(yv, w0.y, as[0]);  as[1] = fmaf(yv, w1.y, as[1]);
            zm[0] = fmaf(yv, w0.z, zm[0]);  zm[1] = fmaf(yv, w1.z, zm[1]);
            zs[0] = fmaf(yv, w0.w, zs[0]);  zs[1] = fmaf(yv, w1.w, zs[1]);
        }
        #pragma unroll
        for (int q = 0; q < 2; ++q) {
            int i = lane + (q << 5);
            out[2 * NI + (size_t)row * I_ + i] = am[q] + bam[q];
            out[3 * NI + (size_t)row * I_ + i] = softplusf(as[q] + bas[q]);
            out[0      + (size_t)row * I_ + i] = zm[q] + bzm[q];
            out[1 * NI + (size_t)row * I_ + i] = softplusf(zs[q] + bzs[q]);
        }
        __syncwarp();
    }
}

// ---------------------------------------------------------------------------
extern "C" void kernel_launch(void* const* d_in, const int* in_sizes, int n_in,
                              void* d_out, int out_size) {
    const float* actions = (const float*)d_in[0];
    const float* hidden  = (const float*)d_in[1];
    const int*   src     = (const int*)d_in[2];
    const int*   dst     = (const int*)d_in[3];
    const float* W_ih    = (const float*)d_in[4];
    const float* W_hh    = (const float*)d_in[5];
    const float* b_ih    = (const float*)d_in[6];
    const float* b_hh    = (const float*)d_in[7];
    const float* ln_g    = (const float*)d_in[8];
    const float* ln_b    = (const float*)d_in[9];
    const float* Wg      = (const float*)d_in[10];
    const float* bg      = (const float*)d_in[11];
    const float* Wa_mu   = (const float*)d_in[12];
    const float* ba_mu   = (const float*)d_in[13];
    const float* Wa_sd   = (const float*)d_in[14];
    const float* ba_sd   = (const float*)d_in[15];
    const float* Wz_mu   = (const float*)d_in[16];
    const float* bz_mu   = (const float*)d_in[17];
    const float* Wz_sd   = (const float*)d_in[18];
    const float* bz_sd   = (const float*)d_in[19];

    float* out   = (float*)d_out;
    float* h_out = out + 4 * N_ * I_;

    cudaFuncSetAttribute(gru_mma_kernel, cudaFuncAttributeMaxDynamicSharedMemorySize, GRU_SMEM);
    cudaFuncSetAttribute(final_kernel, cudaFuncAttributeMaxDynamicSharedMemorySize, FIN_SMEM);

    zero_deg_kernel<<<(N_ + 255) / 256, 256>>>();
    zero_agg_kernel<<<N_ * H_ / 4 / 256, 256>>>();
    degree_kernel<<<E_ / 256, 256>>>(src, dst);
    gru_mma_kernel<<<GRID_GRU, 512, GRU_SMEM>>>(actions, hidden, W_ih, W_hh,
                                                b_ih, b_hh, ln_g, ln_b, h_out);
    scatter_kernel<<<E_ * 32 / 256, 256>>>(src, dst);
    final_kernel<<<148, 512, FIN_SMEM>>>(Wg, bg, Wa_mu, ba_mu, Wa_sd, ba_sd,
                                         Wz_mu, bz_mu, Wz_sd, bz_sd, out);
}